// round 2
// baseline (speedup 1.0000x reference)
#include <cuda_runtime.h>
#include <cstdint>

// ---------------- problem constants ----------------
#define TT 4096       // tokens (B*S)
#define DD 2048       // model dim
#define EE 8          // experts
#define FF 4096       // ffn dim
#define KK 2          // top_k

// ---------------- GEMM tile config -----------------
#define BM 128
#define BN 64
#define BK 32
#define AST (BK + 4)   // 36 floats: A smem row stride (conflict-free for frag loads)
#define BST (BN + 8)   // 72 floats: B smem row stride (conflict-free for frag loads)

#define SMEM_UP   ((2*BM*AST + 4*BK*BST) * 4)   // 73728 B
#define SMEM_DOWN ((2*BM*AST + 2*BK*BST) * 4)   // 55296 B

// ---------------- device scratch --------------------
__device__ int   g_cnt[EE];
__device__ int   g_off[EE];
__device__ int   g_tok[EE * TT];
__device__ float g_wt [EE * TT];
// compact h rows: total assignments = TT*KK = 8192, +BM pad for tile overreads
__device__ float g_h[(size_t)(TT * KK + BM) * FF];

// ---------------- helpers ---------------------------
__device__ __forceinline__ void cp_async16(void* dst_smem, const void* src_glob) {
    uint32_t d = (uint32_t)__cvta_generic_to_shared(dst_smem);
    asm volatile("cp.async.cg.shared.global [%0], [%1], 16;\n" :: "r"(d), "l"(src_glob));
}
__device__ __forceinline__ void cp_commit() {
    asm volatile("cp.async.commit_group;\n" ::: "memory");
}
__device__ __forceinline__ void cp_wait1() {
    asm volatile("cp.async.wait_group 1;\n" ::: "memory");
}
__device__ __forceinline__ void cp_wait0() {
    asm volatile("cp.async.wait_group 0;\n" ::: "memory");
}
__device__ __forceinline__ uint32_t f2tf32(float f) {
    uint32_t r;
    asm("cvt.rna.tf32.f32 %0, %1;\n" : "=r"(r) : "f"(f));
    return r;
}
__device__ __forceinline__ void mma_tf32(float c[4], const uint32_t a[4], const uint32_t b[2]) {
    asm volatile(
        "mma.sync.aligned.m16n8k8.row.col.f32.tf32.tf32.f32 "
        "{%0,%1,%2,%3}, {%4,%5,%6,%7}, {%8,%9}, {%0,%1,%2,%3};\n"
        : "+f"(c[0]), "+f"(c[1]), "+f"(c[2]), "+f"(c[3])
        : "r"(a[0]), "r"(a[1]), "r"(a[2]), "r"(a[3]), "r"(b[0]), "r"(b[1]));
}

// ---------------- kernel 0: zero y + counts ----------
__global__ void zero_kernel(float* __restrict__ y, size_t n) {
    size_t i = (size_t)blockIdx.x * blockDim.x + threadIdx.x;
    size_t stride = (size_t)gridDim.x * blockDim.x;
    for (; i < n; i += stride) y[i] = 0.0f;
    if (blockIdx.x == 0 && threadIdx.x < EE) g_cnt[threadIdx.x] = 0;
}

// ---------------- kernel 1: router -------------------
// grid: TT/8 blocks of 256 threads; one warp per token.
__global__ void router_kernel(const float* __restrict__ x,
                              const float* __restrict__ Wg,
                              float* __restrict__ logits_out,
                              int write_logits) {
    const int warp = threadIdx.x >> 5;
    const int lane = threadIdx.x & 31;
    const int t = blockIdx.x * 8 + warp;
    if (t >= TT) return;

    float acc[EE];
#pragma unroll
    for (int e = 0; e < EE; ++e) acc[e] = 0.0f;

    const float* xr = x + (size_t)t * DD;
    for (int d = lane; d < DD; d += 32) {
        float xv = xr[d];
#pragma unroll
        for (int e = 0; e < EE; ++e) acc[e] += xv * Wg[e * DD + d];
    }
#pragma unroll
    for (int off = 16; off > 0; off >>= 1) {
#pragma unroll
        for (int e = 0; e < EE; ++e)
            acc[e] += __shfl_down_sync(0xffffffffu, acc[e], off);
    }
    if (lane == 0) {
        if (write_logits) {
#pragma unroll
            for (int e = 0; e < EE; ++e) logits_out[(size_t)t * EE + e] = acc[e];
        }
        // top-2 (ties -> lowest index, matching jax.lax.top_k)
        int i1 = 0;
#pragma unroll
        for (int e = 1; e < EE; ++e) if (acc[e] > acc[i1]) i1 = e;
        int i2 = (i1 == 0) ? 1 : 0;
#pragma unroll
        for (int e = 0; e < EE; ++e) if (e != i1 && acc[e] > acc[i2]) i2 = e;
        // normalized pair weights: p1/(p1+p2) = 1/(1+exp(l2-l1))
        float w1 = 1.0f / (1.0f + expf(acc[i2] - acc[i1]));
        float w2 = 1.0f - w1;
        int p1 = atomicAdd(&g_cnt[i1], 1);
        g_tok[i1 * TT + p1] = t; g_wt[i1 * TT + p1] = w1;
        int p2 = atomicAdd(&g_cnt[i2], 1);
        g_tok[i2 * TT + p2] = t; g_wt[i2 * TT + p2] = w2;
    }
}

// ---------------- kernel 2: prefix offsets -----------
__global__ void offsets_kernel() {
    if (threadIdx.x == 0 && blockIdx.x == 0) {
        int s = 0;
#pragma unroll
        for (int e = 0; e < EE; ++e) { g_off[e] = s; s += g_cnt[e]; }
    }
}

// ---------------- kernel 3: up projection ------------
// h[row, f] = silu(x@W1) * (x@W3), per expert, gathered rows.
// grid: (FF/BN, TT/BM, EE), 256 threads.
__global__ void __launch_bounds__(256)
moe_up_kernel(const float* __restrict__ x,
              const float* __restrict__ W1,
              const float* __restrict__ W3) {
    const int e     = blockIdx.z;
    const int mtile = blockIdx.y;
    const int ntile = blockIdx.x;
    const int cnt   = g_cnt[e];
    if (mtile * BM >= cnt) return;

    extern __shared__ float sm[];
    float* As  = sm;                       // 2 * BM * AST
    float* B1s = sm + 2 * BM * AST;        // 2 * BK * BST
    float* B2s = B1s + 2 * BK * BST;       // 2 * BK * BST
    __shared__ int stok[BM];

    const int tid = threadIdx.x;
    if (tid < BM) {
        int idx = mtile * BM + tid;
        stok[tid] = (idx < cnt) ? g_tok[e * TT + idx] : g_tok[e * TT]; // clamp to a valid token
    }
    __syncthreads();

    const float* W1e = W1 + (size_t)e * DD * FF + (size_t)ntile * BN;
    const float* W3e = W3 + (size_t)e * DD * FF + (size_t)ntile * BN;

    auto load_stage = [&](int kt, int buf) {
        float* Ab = As + buf * BM * AST;
#pragma unroll
        for (int v = tid; v < BM * (BK / 4); v += 256) {   // 1024 vec4
            int row = v >> 3;       // BK/4 = 8 vec4 per row
            int c4  = v & 7;
            cp_async16(Ab + row * AST + c4 * 4,
                       x + (size_t)stok[row] * DD + kt + c4 * 4);
        }
        float* B1b = B1s + buf * BK * BST;
        float* B2b = B2s + buf * BK * BST;
#pragma unroll
        for (int v = tid; v < BK * (BN / 4); v += 256) {   // 512 vec4
            int row = v >> 4;       // BN/4 = 16 vec4 per row
            int c4  = v & 15;
            size_t gsrc = (size_t)(kt + row) * FF + c4 * 4;
            cp_async16(B1b + row * BST + c4 * 4, W1e + gsrc);
            cp_async16(B2b + row * BST + c4 * 4, W3e + gsrc);
        }
    };

    const int warp = tid >> 5;
    const int lane = tid & 31;
    const int wm = (warp & 3) * 32;   // 4 warps along M
    const int wn = (warp >> 2) * 32;  // 2 warps along N
    const int g  = lane >> 2;
    const int tg = lane & 3;

    float cg[2][4][4], cu[2][4][4];
#pragma unroll
    for (int mi = 0; mi < 2; ++mi)
#pragma unroll
        for (int ni = 0; ni < 4; ++ni)
#pragma unroll
            for (int j = 0; j < 4; ++j) { cg[mi][ni][j] = 0.f; cu[mi][ni][j] = 0.f; }

    load_stage(0, 0);
    cp_commit();

    const int KS = DD / BK;  // 64
    for (int ks = 0; ks < KS; ++ks) {
        if (ks + 1 < KS) {
            load_stage((ks + 1) * BK, (ks + 1) & 1);
            cp_commit();
            cp_wait1();
        } else {
            cp_wait0();
        }
        __syncthreads();

        const float* Ab  = As  + (ks & 1) * BM * AST;
        const float* B1b = B1s + (ks & 1) * BK * BST;
        const float* B2b = B2s + (ks & 1) * BK * BST;

#pragma unroll
        for (int k8 = 0; k8 < BK / 8; ++k8) {
            uint32_t a[2][4];
#pragma unroll
            for (int mi = 0; mi < 2; ++mi) {
                int r = wm + mi * 16 + g;
                int c = k8 * 8 + tg;
                a[mi][0] = f2tf32(Ab[r * AST + c]);
                a[mi][1] = f2tf32(Ab[(r + 8) * AST + c]);
                a[mi][2] = f2tf32(Ab[r * AST + c + 4]);
                a[mi][3] = f2tf32(Ab[(r + 8) * AST + c + 4]);
            }
            uint32_t b1[4][2], b2[4][2];
#pragma unroll
            for (int ni = 0; ni < 4; ++ni) {
                int col = wn + ni * 8 + g;
                int kr  = k8 * 8 + tg;
                b1[ni][0] = f2tf32(B1b[kr * BST + col]);
                b1[ni][1] = f2tf32(B1b[(kr + 4) * BST + col]);
                b2[ni][0] = f2tf32(B2b[kr * BST + col]);
                b2[ni][1] = f2tf32(B2b[(kr + 4) * BST + col]);
            }
#pragma unroll
            for (int mi = 0; mi < 2; ++mi)
#pragma unroll
                for (int ni = 0; ni < 4; ++ni) {
                    mma_tf32(cg[mi][ni], a[mi], b1[ni]);
                    mma_tf32(cu[mi][ni], a[mi], b2[ni]);
                }
        }
        __syncthreads();
    }

    // epilogue: silu(g)*u -> compact h
    const size_t hbase = (size_t)(g_off[e] + mtile * BM);
    const int mrem = cnt - mtile * BM;
#pragma unroll
    for (int mi = 0; mi < 2; ++mi) {
#pragma unroll
        for (int ni = 0; ni < 4; ++ni) {
            int r0 = wm + mi * 16 + g;
            int c0 = ntile * BN + wn + ni * 8 + tg * 2;
#pragma unroll
            for (int j = 0; j < 4; ++j) {
                int r = r0 + (j >> 1) * 8;
                int c = c0 + (j & 1);
                if (r < mrem) {
                    float gv = cg[mi][ni][j];
                    float uv = cu[mi][ni][j];
                    float s  = gv / (1.0f + __expf(-gv));
                    g_h[(hbase + r) * (size_t)FF + c] = s * uv;
                }
            }
        }
    }
}

// ---------------- kernel 4: down projection ----------
// y[t, :] += w * (h_row @ W2[e])
// grid: (DD/BN, TT/BM, EE), 256 threads.
__global__ void __launch_bounds__(256)
moe_down_kernel(const float* __restrict__ W2, float* __restrict__ y) {
    const int e     = blockIdx.z;
    const int mtile = blockIdx.y;
    const int ntile = blockIdx.x;
    const int cnt   = g_cnt[e];
    if (mtile * BM >= cnt) return;

    extern __shared__ float sm[];
    float* As = sm;                   // 2 * BM * AST
    float* Bs = sm + 2 * BM * AST;    // 2 * BK * BST
    __shared__ int   stok[BM];
    __shared__ float swt[BM];

    const int tid = threadIdx.x;
    if (tid < BM) {
        int idx = mtile * BM + tid;
        int ok = idx < cnt;
        stok[tid] = ok ? g_tok[e * TT + idx] : 0;
        swt[tid]  = ok ? g_wt[e * TT + idx] : 0.f;
    }
    __syncthreads();

    const size_t hbase = (size_t)(g_off[e] + mtile * BM);
    const float* W2e = W2 + (size_t)e * FF * DD + (size_t)ntile * BN;

    auto load_stage = [&](int kt, int buf) {
        float* Ab = As + buf * BM * AST;
#pragma unroll
        for (int v = tid; v < BM * (BK / 4); v += 256) {
            int row = v >> 3;
            int c4  = v & 7;
            cp_async16(Ab + row * AST + c4 * 4,
                       g_h + (hbase + row) * (size_t)FF + kt + c4 * 4);
        }
        float* Bb = Bs + buf * BK * BST;
#pragma unroll
        for (int v = tid; v < BK * (BN / 4); v += 256) {
            int row = v >> 4;
            int c4  = v & 15;
            cp_async16(Bb + row * BST + c4 * 4,
                       W2e + (size_t)(kt + row) * DD + c4 * 4);
        }
    };

    const int warp = tid >> 5;
    const int lane = tid & 31;
    const int wm = (warp & 3) * 32;
    const int wn = (warp >> 2) * 32;
    const int g  = lane >> 2;
    const int tg = lane & 3;

    float c[2][4][4];
#pragma unroll
    for (int mi = 0; mi < 2; ++mi)
#pragma unroll
        for (int ni = 0; ni < 4; ++ni)
#pragma unroll
            for (int j = 0; j < 4; ++j) c[mi][ni][j] = 0.f;

    load_stage(0, 0);
    cp_commit();

    const int KS = FF / BK;  // 128
    for (int ks = 0; ks < KS; ++ks) {
        if (ks + 1 < KS) {
            load_stage((ks + 1) * BK, (ks + 1) & 1);
            cp_commit();
            cp_wait1();
        } else {
            cp_wait0();
        }
        __syncthreads();

        const float* Ab = As + (ks & 1) * BM * AST;
        const float* Bb = Bs + (ks & 1) * BK * BST;

#pragma unroll
        for (int k8 = 0; k8 < BK / 8; ++k8) {
            uint32_t a[2][4];
#pragma unroll
            for (int mi = 0; mi < 2; ++mi) {
                int r = wm + mi * 16 + g;
                int cc = k8 * 8 + tg;
                a[mi][0] = f2tf32(Ab[r * AST + cc]);
                a[mi][1] = f2tf32(Ab[(r + 8) * AST + cc]);
                a[mi][2] = f2tf32(Ab[r * AST + cc + 4]);
                a[mi][3] = f2tf32(Ab[(r + 8) * AST + cc + 4]);
            }
            uint32_t b[4][2];
#pragma unroll
            for (int ni = 0; ni < 4; ++ni) {
                int col = wn + ni * 8 + g;
                int kr  = k8 * 8 + tg;
                b[ni][0] = f2tf32(Bb[kr * BST + col]);
                b[ni][1] = f2tf32(Bb[(kr + 4) * BST + col]);
            }
#pragma unroll
            for (int mi = 0; mi < 2; ++mi)
#pragma unroll
                for (int ni = 0; ni < 4; ++ni)
                    mma_tf32(c[mi][ni], a[mi], b[ni]);
        }
        __syncthreads();
    }

    // epilogue: weighted atomic scatter-add into y
    const int mrem = cnt - mtile * BM;
#pragma unroll
    for (int mi = 0; mi < 2; ++mi) {
#pragma unroll
        for (int ni = 0; ni < 4; ++ni) {
            int r0 = wm + mi * 16 + g;
            int c0 = ntile * BN + wn + ni * 8 + tg * 2;
#pragma unroll
            for (int j = 0; j < 4; ++j) {
                int r = r0 + (j >> 1) * 8;
                int cc = c0 + (j & 1);
                if (r < mrem) {
                    atomicAdd(&y[(size_t)stok[r] * DD + cc], swt[r] * c[mi][ni][j]);
                }
            }
        }
    }
}

// ---------------- launch ------------------------------
extern "C" void kernel_launch(void* const* d_in, const int* in_sizes, int n_in,
                              void* d_out, int out_size) {
    const float* x  = (const float*)d_in[0];
    const float* Wg = (const float*)d_in[1];
    const float* W1 = (const float*)d_in[2];
    const float* W3 = (const float*)d_in[3];
    const float* W2 = (const float*)d_in[4];

    float* y = (float*)d_out;
    float* logits = nullptr;
    int write_logits = 0;
    if ((size_t)out_size >= (size_t)TT * DD + (size_t)TT * EE) {
        logits = y + (size_t)TT * DD;
        write_logits = 1;
    }

    // idempotent; safe during graph capture (not a stream op)
    cudaFuncSetAttribute(moe_up_kernel,
                         cudaFuncAttributeMaxDynamicSharedMemorySize, SMEM_UP);
    cudaFuncSetAttribute(moe_down_kernel,
                         cudaFuncAttributeMaxDynamicSharedMemorySize, SMEM_DOWN);

    zero_kernel<<<4096, 256>>>(y, (size_t)TT * DD);
    router_kernel<<<TT / 8, 256>>>(x, Wg, logits, write_logits);
    offsets_kernel<<<1, 32>>>();
    moe_up_kernel<<<dim3(FF / BN, TT / BM, EE), 256, SMEM_UP>>>(x, W1, W3);
    moe_down_kernel<<<dim3(DD / BN, TT / BM, EE), 256, SMEM_DOWN>>>(W2, y);
}